// round 14
// baseline (speedup 1.0000x reference)
#include <cuda_runtime.h>
#include <cuda_bf16.h>
#include <cstdint>

#define HID   2048
#define NH    16
#define DH    128
#define HARM  64
#define BATCH 2
#define SEQ   2048
#define MTOT  (BATCH*SEQ)   // 4096

// ---------------- scratch (static device globals; no allocs allowed) --------
__device__ __align__(256) __nv_bfloat16 g_xh[MTOT * HID];        // x hi/lo
__device__ __align__(256) __nv_bfloat16 g_xl[MTOT * HID];
__device__ __align__(256) __nv_bfloat16 g_bbh[3 * HARM * HID];   // bases hi/lo
__device__ __align__(256) __nv_bfloat16 g_bbl[3 * HARM * HID];
__device__ __align__(256) __nv_bfloat16 g_ghh[NH * HARM * HARM]; // K2*G hi/lo
__device__ __align__(256) __nv_bfloat16 g_ghl[NH * HARM * HARM];
__device__ __align__(256) __nv_bfloat16 g_chh[HARM * NH * HARM]; // C hi/lo
__device__ __align__(256) __nv_bfloat16 g_chl[HARM * NH * HARM];
__device__ __align__(256) __nv_bfloat16 g_woh[HID * HARM];       // wo hi/lo
__device__ __align__(256) __nv_bfloat16 g_wol[HID * HARM];
__device__ __align__(256) __nv_bfloat16 g_rqh[MTOT * HARM];      // Res_q hi/lo (b,s,64)
__device__ __align__(256) __nv_bfloat16 g_rql[MTOT * HARM];
__device__ __align__(256) __nv_bfloat16 g_rkh[MTOT * HARM];      // Res_k hi/lo (b,s,64)
__device__ __align__(256) __nv_bfloat16 g_rkl[MTOT * HARM];
__device__ __align__(256) __nv_bfloat16 g_rvh[MTOT * HARM];      // Res_v^T hi/lo (b,64,s)
__device__ __align__(256) __nv_bfloat16 g_rvl[MTOT * HARM];
__device__ __align__(256) __nv_bfloat16 g_th[MTOT * NH * HARM];  // T hi/lo (b,h,s,64)
__device__ __align__(256) __nv_bfloat16 g_tl[MTOT * NH * HARM];
__device__ __align__(256) __nv_bfloat16 g_uh[MTOT * NH * HARM];  // U hi/lo (b,s,h,64)
__device__ __align__(256) __nv_bfloat16 g_ul[MTOT * NH * HARM];
__device__ float g_reso4[4 * MTOT * HARM];                       // split-K partials
__device__ __align__(256) __nv_bfloat16 g_resoh[MTOT * HARM];    // res_o hi/lo
__device__ __align__(256) __nv_bfloat16 g_resol[MTOT * HARM];

// ---------------- PTX helpers -------------------------------------------------
__device__ __forceinline__ uint32_t smem_u32(const void* p) {
    uint32_t a;
    asm("{ .reg .u64 t; cvta.to.shared.u64 t, %1; cvt.u32.u64 %0, t; }" : "=r"(a) : "l"(p));
    return a;
}
__device__ __forceinline__ void ldsm4(uint32_t r[4], uint32_t addr) {
    asm volatile("ldmatrix.sync.aligned.m8n8.x4.shared.b16 {%0,%1,%2,%3}, [%4];"
                 : "=r"(r[0]), "=r"(r[1]), "=r"(r[2]), "=r"(r[3]) : "r"(addr));
}
__device__ __forceinline__ void mma16816(float d[4], const uint32_t a[4],
                                         uint32_t b0, uint32_t b1) {
    asm volatile("mma.sync.aligned.m16n8k16.row.col.f32.bf16.bf16.f32 "
                 "{%0,%1,%2,%3}, {%4,%5,%6,%7}, {%8,%9}, {%0,%1,%2,%3};"
                 : "+f"(d[0]), "+f"(d[1]), "+f"(d[2]), "+f"(d[3])
                 : "r"(a[0]), "r"(a[1]), "r"(a[2]), "r"(a[3]), "r"(b0), "r"(b1));
}
__device__ __forceinline__ void cpasync16(uint32_t dst, const void* src) {
    asm volatile("cp.async.cg.shared.global [%0], [%1], 16;" :: "r"(dst), "l"(src));
}
#define CP_COMMIT() asm volatile("cp.async.commit_group;" ::: "memory")
#define CP_WAIT0()  asm volatile("cp.async.wait_group 0;" ::: "memory")

__device__ __forceinline__ float fast_exp2(float x) {
    float y;
    asm("ex2.approx.ftz.f32 %0, %1;" : "=f"(y) : "f"(x));
    return y;
}
__device__ __forceinline__ uint32_t cvt2(float hi, float lo) {   // pack: hi->upper16, lo->lower16
    uint32_t r;
    asm("cvt.rn.bf16x2.f32 %0, %1, %2;" : "=r"(r) : "f"(hi), "f"(lo));
    return r;
}
__device__ __forceinline__ float bfhi_f(uint32_t p) { return __uint_as_float(p & 0xffff0000u); }
__device__ __forceinline__ float bflo_f(uint32_t p) { return __uint_as_float(p << 16); }

// ---------------- shared MMA-GEMM building blocks ------------------------------
// A tile: 128 rows x 64 cols bf16 (hi/lo), rows 128B swizzled.  B tile: 64 x 64.
// Layout inside one chunk buffer: Ah @0 (16KB), Al @16384, Bh @32768 (8KB), Bl @40960.
#define CH_AH 0
#define CH_AL 16384
#define CH_BH 32768
#define CH_BL 40960
#define CHUNK_SZ 49152

template <int NROWS>
__device__ __forceinline__ void stage_rows(uint32_t dst, const __nv_bfloat16* src,
                                           int rstride, int tid) {
#pragma unroll
    for (int i = 0; i < NROWS / 32; i++) {
        int e = tid + i * 256;
        int row = e >> 3, cb = e & 7;
        uint32_t off = row * 128 + ((cb ^ (row & 7)) << 4);
        cpasync16(dst + off, src + (size_t)row * rstride + cb * 8);
    }
}

__device__ __forceinline__ void stage_chunk(uint32_t cbase,
                                            const __nv_bfloat16* Ah, const __nv_bfloat16* Al,
                                            const __nv_bfloat16* Bh, const __nv_bfloat16* Bl,
                                            int rsA, int rsB, int k0, int tid) {
    stage_rows<128>(cbase + CH_AH, Ah + k0, rsA, tid);
    stage_rows<128>(cbase + CH_AL, Al + k0, rsA, tid);
    stage_rows<64>(cbase + CH_BH, Bh + k0, rsB, tid);
    stage_rows<64>(cbase + CH_BL, Bl + k0, rsB, tid);
    CP_COMMIT();
}

// one K=64 chunk of C[128x64] += A[128x64] @ B[64x64]^T, 3-pass hi/lo
__device__ __forceinline__ void mma_chunk(uint32_t cbase, float S[8][4], int lane, int w) {
#pragma unroll
    for (int ks = 0; ks < 4; ks++) {
        int rowA = 16 * w + (lane & 15);
        int cbA = 2 * ks + (lane >> 4);
        uint32_t offA = rowA * 128 + ((cbA ^ (rowA & 7)) << 4);
        uint32_t ah[4], al[4];
        ldsm4(ah, cbase + CH_AH + offA);
        ldsm4(al, cbase + CH_AL + offA);
#pragma unroll
        for (int nb = 0; nb < 4; nb++) {
            int rowB = nb * 16 + (lane & 15);
            uint32_t offB = rowB * 128 + (((2 * ks + (lane >> 4)) ^ (rowB & 7)) << 4);
            uint32_t bh_[4], bl_[4];
            ldsm4(bh_, cbase + CH_BH + offB);
            ldsm4(bl_, cbase + CH_BL + offB);
            mma16816(S[2 * nb],     ah, bh_[0], bh_[2]);
            mma16816(S[2 * nb + 1], ah, bh_[1], bh_[3]);
            mma16816(S[2 * nb],     al, bh_[0], bh_[2]);
            mma16816(S[2 * nb + 1], al, bh_[1], bh_[3]);
            mma16816(S[2 * nb],     ah, bl_[0], bl_[2]);
            mma16816(S[2 * nb + 1], ah, bl_[1], bl_[3]);
        }
    }
}

// ---------------- launch 1: convert x + bases to bf16 hi/lo --------------------
__global__ __launch_bounds__(256)
void conv_kernel(const float* __restrict__ x, const float* __restrict__ bq,
                 const float* __restrict__ bk, const float* __restrict__ bv) {
    int idx = blockIdx.x * 256 + threadIdx.x;
    const int NX = MTOT * HID;
    if (idx < NX) {
        float v = x[idx];
        __nv_bfloat16 hv = __float2bfloat16(v);
        g_xh[idx] = hv;
        g_xl[idx] = __float2bfloat16(v - __bfloat162float(hv));
    } else {
        int e = idx - NX;
        if (e < 3 * HARM * HID) {
            int seg = e / (HARM * HID);
            int off = e - seg * (HARM * HID);
            float v = (seg == 0) ? bq[off] : (seg == 1) ? bk[off] : bv[off];
            __nv_bfloat16 hv = __float2bfloat16(v);
            g_bbh[e] = hv;
            g_bbl[e] = __float2bfloat16(v - __bfloat162float(hv));
        }
    }
}

// ---------------- launch 2: G (K2-folded) and C, emitted hi/lo -----------------
__global__ __launch_bounds__(256)
void gc_kernel(const float* __restrict__ pq, const float* __restrict__ aq,
               const float* __restrict__ pk, const float* __restrict__ ak,
               const float* __restrict__ pv, const float* __restrict__ av,
               const float* __restrict__ bo) {
    __shared__ float sA[64][68];
    __shared__ float sB[64][68];
    const int tx = threadIdx.x, ty = threadIdx.y;
    const int tid = ty * 16 + tx;
    const bool isG = blockIdx.x < 16;
    const int h = isG ? blockIdx.x : blockIdx.x - 16;
    const float K2 = 0.12751742f;   // (1/sqrt(128)) * log2(e)
    float acc[4][4] = {};

    for (int d0 = 0; d0 < DH; d0 += 64) {
        __syncthreads();
        if (isG) {
#pragma unroll
            for (int i = 0; i < 16; i++) {
                int e = tid + i * 256;
                int d = e >> 6, c = e & 63;
                size_t o = (size_t)(h * DH + d0 + d) * HARM + c;
                sA[d][c] = aq[o] * __cosf(pq[o]);
                sB[d][c] = ak[o] * __cosf(pk[o]);
            }
        } else {
#pragma unroll
            for (int i = 0; i < 16; i++) {
                int e = tid + i * 256;
                int j = e >> 6, d = e & 63;
                sA[d][j] = bo[(size_t)j * HID + h * DH + d0 + d];
            }
#pragma unroll
            for (int i = 0; i < 16; i++) {
                int e = tid + i * 256;
                int d = e >> 6, c = e & 63;
                size_t o = (size_t)(h * DH + d0 + d) * HARM + c;
                sB[d][c] = av[o] * __cosf(pv[o]);
            }
        }
        __syncthreads();
#pragma unroll 8
        for (int dd = 0; dd < 64; dd++) {
            float4 a4 = *reinterpret_cast<const float4*>(isG ? &sB[dd][ty * 4] : &sA[dd][ty * 4]);
            float4 b4 = *reinterpret_cast<const float4*>(isG ? &sA[dd][tx * 4] : &sB[dd][tx * 4]);
            float av_[4] = {a4.x, a4.y, a4.z, a4.w};
            float bv_[4] = {b4.x, b4.y, b4.z, b4.w};
#pragma unroll
            for (int i = 0; i < 4; i++)
#pragma unroll
                for (int j = 0; j < 4; j++)
                    acc[i][j] += av_[i] * bv_[j];
        }
    }
#pragma unroll
    for (int i = 0; i < 4; i++) {
        int r = ty * 4 + i;
#pragma unroll
        for (int j = 0; j < 4; j++) {
            int c = tx * 4 + j;
            if (isG) {
                float v = acc[i][j] * K2;
                __nv_bfloat16 hv = __float2bfloat16(v);
                size_t o = ((size_t)h * HARM + r) * HARM + c;
                g_ghh[o] = hv;
                g_ghl[o] = __float2bfloat16(v - __bfloat162float(hv));
            } else {
                float v = acc[i][j];
                __nv_bfloat16 hv = __float2bfloat16(v);
                size_t o = (size_t)r * (NH * HARM) + h * HARM + c;
                g_chh[o] = hv;
                g_chl[o] = __float2bfloat16(v - __bfloat162float(hv));
            }
        }
    }
}

// ---------------- launch 3: wo hi/lo ------------------------------------------
__global__ __launch_bounds__(256)
void wo_kernel(const float* __restrict__ po, const float* __restrict__ ao) {
    int idx = blockIdx.x * 256 + threadIdx.x;
    if (idx < HID * HARM) {
        float v = ao[idx] * cosf(po[idx]);
        __nv_bfloat16 hv = __float2bfloat16(v);
        g_woh[idx] = hv;
        g_wol[idx] = __float2bfloat16(v - __bfloat162float(hv));
    }
}

// ---------------- launch 4: resonances via MMA (grid 3 x 32) -------------------
// C[128x64] = x[128x2048] @ basis_seg[64x2048]^T, double-buffered
__global__ __launch_bounds__(256, 2)
void resmma_kernel() {
    extern __shared__ char sm[];
    const uint32_t sb = smem_u32(sm);
    const int tid = threadIdx.x;
    const int lane = tid & 31, w = tid >> 5;
    const int seg = blockIdx.x;
    const int m0 = blockIdx.y * 128;

    const __nv_bfloat16* Ah = g_xh + (size_t)m0 * HID;
    const __nv_bfloat16* Al = g_xl + (size_t)m0 * HID;
    const __nv_bfloat16* Bh = g_bbh + (size_t)seg * HARM * HID;
    const __nv_bfloat16* Bl = g_bbl + (size_t)seg * HARM * HID;

    float S[8][4] = {};
    int buf = 0;
    stage_chunk(sb, Ah, Al, Bh, Bl, HID, HID, 0, tid);
    for (int kc = 0; kc < HID / 64; kc++) {
        CP_WAIT0();
        __syncthreads();
        if (kc + 1 < HID / 64)
            stage_chunk(sb + (buf ^ 1) * CHUNK_SZ, Ah, Al, Bh, Bl, HID, HID, (kc + 1) * 64, tid);
        mma_chunk(sb + buf * CHUNK_SZ, S, lane, w);
        buf ^= 1;
    }

    // epilogue
    const int row0 = m0 + 16 * w + (lane >> 2);
#pragma unroll
    for (int nb = 0; nb < 4; nb++) {
#pragma unroll
        for (int q = 0; q < 4; q++) {
            int m = (q & 1) ? row0 + 8 : row0;
            int c = nb * 16 + ((q >> 1) ? 8 : 0) + (lane & 3) * 2;
            float v0 = S[2 * nb + (q >> 1)][(q & 1) ? 2 : 0];
            float v1 = S[2 * nb + (q >> 1)][(q & 1) ? 3 : 1];
            uint32_t hp = cvt2(v1, v0);
            uint32_t lp = cvt2(v1 - bfhi_f(hp), v0 - bflo_f(hp));
            if (seg == 0) {
                size_t o = (size_t)m * HARM + c;
                *reinterpret_cast<uint32_t*>(&g_rqh[o]) = hp;
                *reinterpret_cast<uint32_t*>(&g_rql[o]) = lp;
            } else if (seg == 1) {
                size_t o = (size_t)m * HARM + c;
                *reinterpret_cast<uint32_t*>(&g_rkh[o]) = hp;
                *reinterpret_cast<uint32_t*>(&g_rkl[o]) = lp;
            } else {
                int b = m >> 11, s = m & 2047;
                size_t o0 = ((size_t)b * HARM + c) * SEQ + s;
                size_t o1 = ((size_t)b * HARM + c + 1) * SEQ + s;
                g_rvh[o0] = __ushort_as_bfloat16((unsigned short)(hp & 0xffff));
                g_rvl[o0] = __ushort_as_bfloat16((unsigned short)(lp & 0xffff));
                g_rvh[o1] = __ushort_as_bfloat16((unsigned short)(hp >> 16));
                g_rvl[o1] = __ushort_as_bfloat16((unsigned short)(lp >> 16));
            }
        }
    }
}

// ---------------- launch 5: T via MMA (grid 16 x 32), K=64 ---------------------
__global__ __launch_bounds__(256, 2)
void tprojmma_kernel() {
    extern __shared__ char sm[];
    const uint32_t sb = smem_u32(sm);
    const int tid = threadIdx.x;
    const int lane = tid & 31, w = tid >> 5;
    const int h = blockIdx.x;
    const int m0 = blockIdx.y * 128;

    stage_chunk(sb, g_rqh + (size_t)m0 * HARM, g_rql + (size_t)m0 * HARM,
                g_ghh + (size_t)h * HARM * HARM, g_ghl + (size_t)h * HARM * HARM,
                HARM, HARM, 0, tid);
    float S[8][4] = {};
    CP_WAIT0();
    __syncthreads();
    mma_chunk(sb, S, lane, w);

    const int row0 = m0 + 16 * w + (lane >> 2);
#pragma unroll
    for (int nb = 0; nb < 4; nb++) {
#pragma unroll
        for (int q = 0; q < 4; q++) {
            int m = (q & 1) ? row0 + 8 : row0;
            int c = nb * 16 + ((q >> 1) ? 8 : 0) + (lane & 3) * 2;
            float v0 = S[2 * nb + (q >> 1)][(q & 1) ? 2 : 0];
            float v1 = S[2 * nb + (q >> 1)][(q & 1) ? 3 : 1];
            uint32_t hp = cvt2(v1, v0);
            uint32_t lp = cvt2(v1 - bfhi_f(hp), v0 - bflo_f(hp));
            int b = m >> 11, s = m & 2047;
            size_t o = (((size_t)(b * NH + h)) * SEQ + s) * HARM + c;
            *reinterpret_cast<uint32_t*>(&g_th[o]) = hp;
            *reinterpret_cast<uint32_t*>(&g_tl[o]) = lp;
        }
    }
}

// ---------------- launch 6: flash attention (mainloop unchanged) ---------------
#define BQ 128
#define BK 64
#define OFF_T  0
#define OFF_B0 32768
#define BUFSZ  32768
#define FA_SMEM (OFF_B0 + 2*BUFSZ)   // 98304

__device__ __forceinline__ void prefetch_tile(uint32_t sb, int buf, int b, int kt, int tid) {
    const uint32_t base = sb + OFF_B0 + buf * BUFSZ;
    const __nv_bfloat16* rk_h = g_rkh + ((size_t)b * SEQ + kt * BK) * HARM;
    const __nv_bfloat16* rk_l = g_rkl + ((size_t)b * SEQ + kt * BK) * HARM;
#pragma unroll
    for (int i = 0; i < 2; i++) {
        int e = tid + i * 256;
        int row = e >> 3, cb = e & 7;
        uint32_t off = row * 128 + ((cb ^ (row & 7)) << 4);
        cpasync16(base + off,        rk_h + row * HARM + cb * 8);
        cpasync16(base + 8192 + off, rk_l + row * HARM + cb * 8);
    }
    const __nv_bfloat16* rv_h = g_rvh + (size_t)b * HARM * SEQ + kt * BK;
    const __nv_bfloat16* rv_l = g_rvl + (size_t)b * HARM * SEQ + kt * BK;
#pragma unroll
    for (int i = 0; i < 2; i++) {
        int e = tid + i * 256;
        int row = e >> 3, cb = e & 7;
        uint32_t off = row * 128 + ((cb ^ (row & 7)) << 4);
        cpasync16(base + 16384 + off, rv_h + (size_t)row * SEQ + cb * 8);
        cpasync16(base + 24576 + off, rv_l + (size_t)row * SEQ + cb * 8);
    }
    CP_COMMIT();
}

__global__ __launch_bounds__(256, 2)
void flash_mma_kernel() {
    extern __shared__ char sm[];
    const uint32_t sb = smem_u32(sm);
    const int tid = threadIdx.x;
    const int lane = tid & 31, w = tid >> 5;
    const int bh = blockIdx.y;
    const int q0 = blockIdx.x * BQ;
    const int b = bh >> 4, h = bh & 15;

    {
        const __nv_bfloat16* th = g_th + ((size_t)bh * SEQ + q0) * HARM;
        const __nv_bfloat16* tl = g_tl + ((size_t)bh * SEQ + q0) * HARM;
#pragma unroll
        for (int i = 0; i < 4; i++) {
            int e = tid + i * 256;
            int row = e >> 3, cb = e & 7;
            uint32_t off = row * 128 + ((cb ^ (row & 7)) << 4);
            *reinterpret_cast<uint4*>(sm + OFF_T + off) =
                *reinterpret_cast<const uint4*>(th + row * HARM + cb * 8);
            *reinterpret_cast<uint4*>(sm + OFF_T + 16384 + off) =
                *reinterpret_cast<const uint4*>(tl + row * HARM + cb * 8);
        }
    }
    prefetch_tile(sb, 0, b, 0, tid);
    __syncthreads();

    float U[8][4] = {};
    float rs0 = 0.0f, rs1 = 0.0f;
    float mx0 = -3.0e38f, mx1 = -3.0e38f;
    int buf = 0;

    for (int kt = 0; kt < SEQ / BK; kt++) {
        CP_WAIT0();
        __syncthreads();
        if (kt + 1 < SEQ / BK) prefetch_tile(sb, buf ^ 1, b, kt + 1, tid);

        const uint32_t kb = sb + OFF_B0 + buf * BUFSZ;

        float S[8][4] = {};
#pragma unroll
        for (int ks = 0; ks < 4; ks++) {
            int rowA = 16 * w + (lane & 15);
            int cbA = 2 * ks + (lane >> 4);
            uint32_t offA = rowA * 128 + ((cbA ^ (rowA & 7)) << 4);
            uint32_t th[4], tl[4];
            ldsm4(th, sb + OFF_T + offA);
            ldsm4(tl, sb + OFF_T + 16384 + offA);
#pragma unroll
            for (int nb = 0; nb < 4; nb++) {
                int rowB = nb * 16 + (lane & 15);
                uint32_t offB = rowB * 128 + (((2 * ks + (lane >> 4)) ^ (rowB & 7)) << 4);
                uint32_t kh[4], kl[4];
                ldsm4(kh, kb + offB);
                ldsm4(kl, kb + 8192 + offB);
                mma16816(S[2 * nb],     th, kh[0], kh[2]);
                mma16816(S[2 * nb + 1], th, kh[1], kh[3]);
                mma16816(S[2 * nb],     tl, kh[0], kh[2]);
                mma16816(S[2 * nb + 1], tl, kh[1], kh[3]);
                mma16816(S[2 * nb],     th, kl[0], kl[2]);
                mma16816(S[2 * nb + 1], th, kl[1], kl[3]);
            }
        }

        float tm0 = -3.0e38f, tm1 = -3.0e38f;
#pragma unroll
        for (int t = 0; t < 8; t++) {
            tm0 = fmaxf(tm0, fmaxf(S[t][0], S[t][1]));
            tm1 = fmaxf(tm1, fmaxf(S[t][2], S[t][3]));
        }
        tm0 = fmaxf(tm0, __shfl_xor_sync(0xffffffffu, tm0, 1));
        tm0 = fmaxf(tm0, __shfl_xor_sync(0xffffffffu, tm0, 2));
        tm1 = fmaxf(tm1, __shfl_xor_sync(0xffffffffu, tm1, 1));
        tm1 = fmaxf(tm1, __shfl_xor_sync(0xffffffffu, tm1, 2));

        float nm0 = fmaxf(mx0, tm0);
        float nm1 = fmaxf(mx1, tm1);
        float c0 = fast_exp2(mx0 - nm0);
        float c1 = fast_exp2(mx1 - nm1);
        mx0 = nm0; mx1 = nm1;

        float ls0 = 0.0f, ls1 = 0.0f;
#pragma unroll
        for (int t = 0; t < 8; t++) {
            float e0 = fast_exp2(S[t][0] - nm0);
            float e1 = fast_exp2(S[t][1] - nm0);
            float e2 = fast_exp2(S[t][2] - nm1);
            float e3 = fast_exp2(S[t][3] - nm1);
            ls0 += e0 + e1;
            ls1 += e2 + e3;
            S[t][0] = e0; S[t][1] = e1; S[t][2] = e2; S[t][3] = e3;
        }
        rs0 = rs0 * c0 + ls0;
        rs1 = rs1 * c1 + ls1;
#pragma unroll
        for (int t = 0; t < 8; t++) {
            U[t][0] *= c0; U[t][1] *= c0;
            U[t][2] *= c1; U[t][3] *= c1;
        }

#pragma unroll
        for (int ks2 = 0; ks2 < 4; ks2++) {
            uint32_t ph[4], pl[4];
            ph[0] = cvt2(S[2 * ks2][1],     S[2 * ks2][0]);
            ph[1] = cvt2(S[2 * ks2][3],     S[2 * ks2][2]);
            ph[2] = cvt2(S[2 * ks2 + 1][1], S[2 * ks2 + 1][0]);
            ph[3] = cvt2(S[2 * ks2 + 1][3], S[2 * ks2 + 1][2]);
            pl[0] = cvt2(S[2 * ks2][1]     - bfhi_f(ph[0]), S[2 * ks2][0]     - bflo_f(ph[0]));
            pl[1] = cvt2(S[2 * ks2][3]     - bfhi_f(ph[1]), S[2 * ks2][2]     - bflo_f(ph[1]));
            pl[2] = cvt2(S[2 * ks2 + 1][1] - bfhi_f(ph[2]), S[2 * ks2 + 1][0] - bflo_f(ph[2]));
            pl[3] = cvt2(S[2 * ks2 + 1][3] - bfhi_f(ph[3]), S[2 * ks2 + 1][2] - bflo_f(ph[3]));
#pragma unroll
            for (int nb = 0; nb < 4; nb++) {
                int rowB = nb * 16 + (lane & 15);
                uint32_t offB = rowB * 128 + (((2 * ks2 + (lane >> 4)) ^ (rowB & 7)) << 4);
                uint32_t vh[4], vl[4];
                ldsm4(vh, kb + 16384 + offB);
                ldsm4(vl, kb + 24576 + offB);
                mma16816(U[2 * nb],     ph, vh[0], vh[2]);
                mma16816(U[2 * nb + 1], ph, vh[1], vh[3]);
                mma16816(U[2 * nb],     ph, vl[0], vl[2]);
                mma16816(U[2 * nb + 1], ph, vl[1], vl[3]);
                mma16816(U[2 * nb],     pl, vh[0], vh[2]);
                mma16816(U[2 * nb + 1], pl, vh[1], vh[3]);
            }
        }
        buf ^= 1;
    }

    // epilogue: normalize, emit U hi/lo bf16 to (b,s,h,64)
    rs0 += __shfl_xor_sync(0xffffffffu, rs0, 1);
    rs0 += __shfl_xor_sync(0xffffffffu, rs0, 2);
    rs1 += __shfl_xor_sync(0xffffffffu, rs1, 1);
    rs1 += __shfl_xor_sync(0xffffffffu, rs1, 2);
    const float inv0 = 1.0f / rs0;
    const float inv1 = 1.0f / rs1;

    const int row0 = q0 + 16 * w + (lane >> 2);
#pragma unroll
    for (int nb = 0; nb < 4; nb++) {
#pragma unroll
        for (int q = 0; q < 4; q++) {
            int m = (q & 1) ? row0 + 8 : row0;
            float inv = (q & 1) ? inv1 : inv0;
            int c = nb * 16 + ((q >> 1) ? 8 : 0) + (lane & 3) * 2;
            float v0 = U[2 * nb + (q >> 1)][(q & 1) ? 2 : 0] * inv;
            float v1 = U[2 * nb + (q >> 1)][(q & 1) ? 3 : 1] * inv;
            uint32_t hp = cvt2(v1, v0);
            uint32_t lp = cvt2(v1 - bfhi_f(hp), v0 - bflo_f(hp));
            size_t o = (((size_t)(b * SEQ + m)) * NH + h) * HARM + c;
            *reinterpret_cast<uint32_t*>(&g_uh[o]) = hp;
            *reinterpret_cast<uint32_t*>(&g_ul[o]) = lp;
        }
    }
}

// ---------------- launch 7: uproj via MMA, split-K x4 (grid 4 x 32) ------------
__global__ __launch_bounds__(256, 2)
void uprojmma_kernel() {
    extern __shared__ char sm[];
    const uint32_t sb = smem_u32(sm);
    const int tid = threadIdx.x;
    const int lane = tid & 31, w = tid >> 5;
    const int kc = blockIdx.x;
    const int m0 = blockIdx.y * 128;

    const __nv_bfloat16* Ah = g_uh + (size_t)m0 * (NH * HARM) + kc * 256;
    const __nv_bfloat16* Al = g_ul + (size_t)m0 * (NH * HARM) + kc * 256;
    const __nv_bfloat16* Bh = g_chh + kc * 256;
    const __nv_bfloat16* Bl = g_chl + kc * 256;

    float S[8][4] = {};
    int buf = 0;
    stage_chunk(sb, Ah, Al, Bh, Bl, NH * HARM, NH * HARM, 0, tid);
    for (int c = 0; c < 4; c++) {
        CP_WAIT0();
        __syncthreads();
        if (c + 1 < 4)
            stage_chunk(sb + (buf ^ 1) * CHUNK_SZ, Ah, Al, Bh, Bl,
                        NH * HARM, NH * HARM, (c + 1) * 64, tid);
        mma_chunk(sb + buf * CHUNK_SZ, S, lane, w);
        buf ^= 1;
    }

    float* out = g_reso4 + (size_t)kc * MTOT * HARM;
    const int row0 = m0 + 16 * w + (lane >> 2);
#pragma unroll
    for (int nb = 0; nb < 4; nb++) {
#pragma unroll
        for (int q = 0; q < 4; q++) {
            int m = (q & 1) ? row0 + 8 : row0;
            int c = nb * 16 + ((q >> 1) ? 8 : 0) + (lane & 3) * 2;
            float v0 = S[2 * nb + (q >> 1)][(q & 1) ? 2 : 0];
            float v1 = S[2 * nb + (q >> 1)][(q & 1) ? 3 : 1];
            *reinterpret_cast<float2*>(&out[(size_t)m * HARM + c]) = make_float2(v0, v1);
        }
    }
}

// ---------------- launch 8: sum partials -> res_o hi/lo ------------------------
__global__ __launch_bounds__(256)
void sumconv_kernel() {
    int idx = blockIdx.x * 256 + threadIdx.x;
    if (idx < MTOT * HARM) {
        float v = g_reso4[idx] + g_reso4[idx + MTOT * HARM]
                + g_reso4[idx + 2 * MTOT * HARM] + g_reso4[idx + 3 * MTOT * HARM];
        __nv_bfloat16 hv = __float2bfloat16(v);
        g_resoh[idx] = hv;
        g_resol[idx] = __float2bfloat16(v - __bfloat162float(hv));
    }
}

// ---------------- launch 9: out via MMA (grid 32 x 32), K=64 -------------------
__global__ __launch_bounds__(256, 2)
void outmma_kernel(float* __restrict__ C) {
    extern __shared__ char sm[];
    const uint32_t sb = smem_u32(sm);
    const int tid = threadIdx.x;
    const int lane = tid & 31, w = tid >> 5;
    const int n0 = blockIdx.x * 64;
    const int m0 = blockIdx.y * 128;

    stage_chunk(sb, g_resoh + (size_t)m0 * HARM, g_resol + (size_t)m0 * HARM,
                g_woh + (size_t)n0 * HARM, g_wol + (size_t)n0 * HARM,
                HARM, HARM, 0, tid);
    float S[8][4] = {};
    CP_WAIT0();
    __syncthreads();
    mma_chunk(sb, S, lane, w);

    const int row0 = m0 + 16 * w + (lane >> 2);
#pragma unroll
    for (int nb = 0; nb < 4; nb++) {
#pragma unroll
        for (int q = 0; q < 4; q++) {
            int m = (q & 1) ? row0 + 8 : row0;
            int c = n0 + nb * 16 + ((q >> 1) ? 8 : 0) + (lane & 3) * 2;
            float v0 = S[2 * nb + (q >> 1)][(q & 1) ? 2 : 0];
            float v1 = S[2 * nb + (q >> 1)][(q & 1) ? 3 : 1];
            *reinterpret_cast<float2*>(&C[(size_t)m * HID + c]) = make_float2(v0, v1);
        }
    }
}

// ---------------- launcher ----------------------------------------------------
extern "C" void kernel_launch(void* const* d_in, const int* in_sizes, int n_in,
                              void* d_out, int out_size) {
    const float* x  = (const float*)d_in[0];
    const float* bq = (const float*)d_in[1];
    const float* pq = (const float*)d_in[2];
    const float* aq = (const float*)d_in[3];
    const float* bk = (const float*)d_in[4];
    const float* pk = (const float*)d_in[5];
    const float* ak = (const float*)d_in[6];
    const float* bv = (const float*)d_in[7];
    const float* pv = (const float*)d_in[8];
    const float* av = (const float*)d_in[9];
    const float* bo = (const float*)d_in[10];
    const float* po = (const float*)d_in[11];
    const float* ao = (const float*)d_in[12];
    float* out = (float*)d_out;

    dim3 thr(16, 16);
    const int DBUF = 2 * CHUNK_SZ;   // 98304
    cudaFuncSetAttribute(resmma_kernel,  cudaFuncAttributeMaxDynamicSharedMemorySize, DBUF);
    cudaFuncSetAttribute(tprojmma_kernel, cudaFuncAttributeMaxDynamicSharedMemorySize, CHUNK_SZ);
    cudaFuncSetAttribute(flash_mma_kernel, cudaFuncAttributeMaxDynamicSharedMemorySize, FA_SMEM);
    cudaFuncSetAttribute(uprojmma_kernel, cudaFuncAttributeMaxDynamicSharedMemorySize, DBUF);
    cudaFuncSetAttribute(outmma_kernel,  cudaFuncAttributeMaxDynamicSharedMemorySize, CHUNK_SZ);

    // 1: convert x + bases to hi/lo
    conv_kernel<<<(MTOT * HID + 3 * HARM * HID + 255) / 256, 256>>>(x, bq, bk, bv);
    // 2: G (K2-folded) and C, hi/lo
    gc_kernel<<<32, thr>>>(pq, aq, pk, ak, pv, av, bo);
    // 3: wo hi/lo
    wo_kernel<<<(HID * HARM + 255) / 256, 256>>>(po, ao);
    // 4: resonances (MMA)
    resmma_kernel<<<dim3(3, MTOT / 128), 256, DBUF>>>();
    // 5: T (MMA)
    tprojmma_kernel<<<dim3(NH, MTOT / 128), 256, CHUNK_SZ>>>();
    // 6: attention
    flash_mma_kernel<<<dim3(SEQ / BQ, BATCH * NH), 256, FA_SMEM>>>();
    // 7: res_o partials (MMA, split-K x4)
    uprojmma_kernel<<<dim3(4, MTOT / 128), 256, DBUF>>>();
    // 8: sum + convert
    sumconv_kernel<<<(MTOT * HARM + 255) / 256, 256>>>();
    // 9: out (MMA)
    outmma_kernel<<<dim3(HID / 64, MTOT / 128), 256, CHUNK_SZ>>>(out);
}